// round 17
// baseline (speedup 1.0000x reference)
#include <cuda_runtime.h>
#include <cuda_fp16.h>
#include <stdint.h>

// Problem constants
#define NN 8192
#define MM 8192
#define DD 64
#define TILE 128
#define NTILE (NN / TILE)   // 64

// log2(e) = 1.4426950409; (log2 e)^2 = 2.0813689810; -2*(log2 e)^2 = -4.1627379620
#define C_L2E2   2.0813690f
#define C_M2L2E2 -4.1627379f
#define C_LN2    0.69314718f

// ---------------- device scratch ----------------
__device__ uint4 g_xh[NN * 8];
__device__ uint4 g_xl[NN * 8];
__device__ uint4 g_yh[NN * 8];
__device__ uint4 g_yl[NN * 8];

__device__ float g_xsq[NN];
__device__ float g_ysq[MM];
__device__ float g_rowsum[NN];
__device__ float g_colsum[MM];
__device__ unsigned long long g_rowmaxp[NN];
__device__ unsigned long long g_colmaxp[MM];
__device__ float g_lp_rows[NN];
__device__ float g_lp_cols[MM];
__device__ int   g_choice_rows[NN];
__device__ int   g_choice_cols[MM];

// ---------------- helpers ----------------
// s2 = (log2e)^2 * dist^2, always >= ~50. Key = bits(s2) (positive-float unsigned
// order) with tie-break index packed in the low bits; umin tracking.
// At reduction boundaries: hi32 = ~(key & mask) (bigger=better), lo32 = ~global_idx.
__device__ __forceinline__ float ex2a(float x) {
    float y; asm("ex2.approx.ftz.f32 %0, %1;" : "=f"(y) : "f"(x)); return y;
}
__device__ __forceinline__ float sqrta(float x) {
    float y; asm("sqrt.approx.ftz.f32 %0, %1;" : "=f"(y) : "f"(x)); return y;
}
__device__ __forceinline__ void ffma2(unsigned long long& d,
                                      unsigned long long a,
                                      unsigned long long b) {
    asm("fma.rn.f32x2 %0, %1, %2, %0;" : "+l"(d) : "l"(a), "l"(b));
}
__device__ __forceinline__ unsigned long long mul2(unsigned long long a,
                                                   unsigned long long b) {
    unsigned long long r;
    asm("mul.rn.f32x2 %0, %1, %2;" : "=l"(r) : "l"(a), "l"(b));
    return r;
}
__device__ __forceinline__ unsigned long long fma2v(unsigned long long a,
                                                    unsigned long long b,
                                                    unsigned long long c) {
    unsigned long long d = c;
    asm("fma.rn.f32x2 %0, %1, %2, %0;" : "+l"(d) : "l"(a), "l"(b));
    return d;
}
__device__ __forceinline__ unsigned long long bcast2(float a) {
    unsigned long long r;
    asm("mov.b64 %0, {%1, %1};" : "=l"(r) : "f"(a));
    return r;
}
__device__ __forceinline__ void unpack2(float& lo, float& hi, unsigned long long v) {
    asm("mov.b64 {%0, %1}, %2;" : "=f"(lo), "=f"(hi) : "l"(v));
}
__device__ __forceinline__ uint32_t smem_u32(const void* p) {
    uint32_t a;
    asm("{ .reg .u64 t; cvta.to.shared.u64 t, %1; cvt.u32.u64 %0, t; }"
        : "=r"(a) : "l"(p));
    return a;
}
__device__ __forceinline__ void ldsm4(uint32_t& r0, uint32_t& r1, uint32_t& r2,
                                      uint32_t& r3, uint32_t addr) {
    asm volatile("ldmatrix.sync.aligned.m8n8.x4.shared.b16 {%0,%1,%2,%3}, [%4];"
                 : "=r"(r0), "=r"(r1), "=r"(r2), "=r"(r3) : "r"(addr));
}
__device__ __forceinline__ void mma_f16(float& d0, float& d1, float& d2, float& d3,
                                        uint32_t a0, uint32_t a1, uint32_t a2, uint32_t a3,
                                        uint32_t b0, uint32_t b1) {
    asm("mma.sync.aligned.m16n8k16.row.col.f32.f16.f16.f32 "
        "{%0,%1,%2,%3}, {%4,%5,%6,%7}, {%8,%9}, {%0,%1,%2,%3};"
        : "+f"(d0), "+f"(d1), "+f"(d2), "+f"(d3)
        : "r"(a0), "r"(a1), "r"(a2), "r"(a3), "r"(b0), "r"(b1));
}

// ---------------- prep: zero accums, sqnorms, fp16 2-way split ----------------
__global__ void prep_kernel(const float* __restrict__ x, const float* __restrict__ y) {
    int t = blockIdx.x * blockDim.x + threadIdx.x;
    if (t < NN) {
        g_rowsum[t] = 0.f; g_colsum[t] = 0.f;
        g_rowmaxp[t] = 0ull; g_colmaxp[t] = 0ull;
    }
    if (t >= 2 * NN) return;
    int r = (t < NN) ? t : (t - NN);
    const float* src = (t < NN) ? (x + (size_t)r * DD) : (y + (size_t)r * DD);
    __half2* ph = ((t < NN) ? (__half2*)g_xh : (__half2*)g_yh) + (size_t)r * 32;
    __half2* pl = ((t < NN) ? (__half2*)g_xl : (__half2*)g_yl) + (size_t)r * 32;

    float s = 0.f;
#pragma unroll
    for (int k = 0; k < 32; ++k) {
        float2 v = ((const float2*)src)[k];
        s += v.x * v.x + v.y * v.y;
        __half ha = __float2half(v.x);
        __half la = __float2half(v.x - __half2float(ha));
        __half hb = __float2half(v.y);
        __half lb = __float2half(v.y - __half2float(hb));
        __half2 vh; vh.x = ha; vh.y = hb;
        __half2 vl; vl.x = la; vl.y = lb;
        ph[k] = vh; pl[k] = vl;
    }
    if (t < NN) g_xsq[r] = s; else g_ysq[r] = s;
}

// ---------------- smem layouts (union of the two methods) ----------------
#define XT_STRIDE 132
#define F_XT 0
#define F_YT (F_XT + 64 * XT_STRIDE * 4)
#define F_SXQ (F_YT + 64 * XT_STRIDE * 4)
#define F_SYQ (F_SXQ + 512)
#define F_CSUM (F_SYQ + 512)
#define F_CMAX ((F_CSUM + 512 + 15) & ~15)
#define F_END (F_CMAX + 1024)
#define H_SXQ  (4 * 16384)
#define H_SYQ  (H_SXQ + 512)
#define H_CSUM (H_SYQ + 512)
#define H_RSUM (H_CSUM + 512)
#define H_CMAX (H_RSUM + 512)
#define H_RMAX (H_CMAX + 1024)
#define H_END  (H_RMAX + 1024)
#define SMEM_TOTAL (F_END > H_END ? F_END : H_END)

// ---------------- main hybrid kernel ----------------
__global__ void __launch_bounds__(256, 2)
matcher_main_kernel(const float* __restrict__ x, const float* __restrict__ y) {
    extern __shared__ char smem[];
    const int tid = threadIdx.x;
    const int ibase = blockIdx.y * TILE;
    const int jbase = blockIdx.x * TILE;
    const int bid = blockIdx.y * gridDim.x + blockIdx.x;
    const int method = (bid / 148) & 1;

    if (method == 0) {
        // ================= F branch: FFMA2 fp32 =================
        float* xT = (float*)(smem + F_XT);
        float* yT = (float*)(smem + F_YT);
        float* sxq = (float*)(smem + F_SXQ);
        float* syq = (float*)(smem + F_SYQ);
        float* scsum = (float*)(smem + F_CSUM);
        unsigned long long* scmax = (unsigned long long*)(smem + F_CMAX);

        const int tx = tid & 15;
        const int ty = tid >> 4;
        const int i0 = ty * 8;
        const int j0 = tx * 8;

#pragma unroll
        for (int k = tid; k < TILE * (DD / 4); k += 256) {
            int r = k >> 4;
            int c4 = k & 15;
            float4 vx = *(const float4*)(x + (size_t)(ibase + r) * DD + c4 * 4);
            float4 vy = *(const float4*)(y + (size_t)(jbase + r) * DD + c4 * 4);
            int d = c4 * 4;
            xT[(d + 0) * XT_STRIDE + r] = vx.x;
            xT[(d + 1) * XT_STRIDE + r] = vx.y;
            xT[(d + 2) * XT_STRIDE + r] = vx.z;
            xT[(d + 3) * XT_STRIDE + r] = vx.w;
            yT[(d + 0) * XT_STRIDE + r] = vy.x;
            yT[(d + 1) * XT_STRIDE + r] = vy.y;
            yT[(d + 2) * XT_STRIDE + r] = vy.z;
            yT[(d + 3) * XT_STRIDE + r] = vy.w;
        }
        if (tid < 128) sxq[tid] = g_xsq[ibase + tid];
        else           syq[tid - 128] = g_ysq[jbase + tid - 128];
        __syncthreads();

        unsigned long long acc2[8][4];
#pragma unroll
        for (int r = 0; r < 8; ++r)
#pragma unroll
            for (int c2 = 0; c2 < 4; ++c2) acc2[r][c2] = 0ull;

#pragma unroll 4
        for (int d = 0; d < DD; ++d) {
            ulonglong2 p0 = *(const ulonglong2*)&yT[d * XT_STRIDE + j0];
            ulonglong2 p1 = *(const ulonglong2*)&yT[d * XT_STRIDE + j0 + 4];
            unsigned long long bp[4] = { p0.x, p0.y, p1.x, p1.y };
            float4 t0 = *(const float4*)&xT[d * XT_STRIDE + i0];
            float4 t1 = *(const float4*)&xT[d * XT_STRIDE + i0 + 4];
            unsigned long long av[8];
            av[0] = bcast2(t0.x); av[1] = bcast2(t0.y);
            av[2] = bcast2(t0.z); av[3] = bcast2(t0.w);
            av[4] = bcast2(t1.x); av[5] = bcast2(t1.y);
            av[6] = bcast2(t1.z); av[7] = bcast2(t1.w);
#pragma unroll
            for (int r = 0; r < 8; ++r)
#pragma unroll
                for (int c2 = 0; c2 < 4; ++c2)
                    ffma2(acc2[r][c2], av[r], bp[c2]);
        }

        // -------- slim epilogue v2: sq-domain keys, packed scale math --------
        const unsigned long long C2P = bcast2(C_L2E2);
        const unsigned long long CM4 = bcast2(C_M2L2E2);
        ulonglong2 yp0 = *(const ulonglong2*)&syq[j0];
        ulonglong2 yp1 = *(const ulonglong2*)&syq[j0 + 4];
        unsigned long long s2y[4] = { mul2(yp0.x, C2P), mul2(yp0.y, C2P),
                                      mul2(yp1.x, C2P), mul2(yp1.y, C2P) };

        float rsum[8], csum[8];
        unsigned rkmin[8], ckmin[8];
#pragma unroll
        for (int r = 0; r < 8; ++r) { rsum[r] = 0.f; rkmin[r] = 0xFFFFFFFFu; }
#pragma unroll
        for (int c = 0; c < 8; ++c) { csum[c] = 0.f; ckmin[c] = 0xFFFFFFFFu; }

#pragma unroll
        for (int r = 0; r < 8; ++r) {
            unsigned long long xq2 = bcast2(sxq[i0 + r]);
#pragma unroll
            for (int c2 = 0; c2 < 4; ++c2) {
                unsigned long long s2p = fma2v(xq2, C2P, s2y[c2]);
                ffma2(s2p, acc2[r][c2], CM4);   // s2 = l2e2*(xq+yq) - 2*l2e2*acc
                float s0, s1;
                unpack2(s0, s1, s2p);
#pragma unroll
                for (int u = 0; u < 2; ++u) {
                    const int c = 2 * c2 + u;
                    float s2 = u ? s1 : s0;
                    unsigned b = __float_as_uint(s2) & 0xFFFFFFF8u;
                    rkmin[r] = min(rkmin[r], b | (unsigned)c);
                    ckmin[c] = min(ckmin[c], b | (unsigned)r);
                    float d2 = sqrta(s2);
                    float pp = ex2a(-d2);
                    rsum[r] += pp;
                    csum[c] += pp;
                }
            }
        }

        // row reduce across tx (16-lane groups within warp)
#pragma unroll
        for (int r = 0; r < 8; ++r) {
            unsigned km = rkmin[r];
            unsigned gj = (unsigned)(jbase + j0 + (int)(km & 7u));
            unsigned long long rp = (((unsigned long long)(~(km & 0xFFFFFFF8u))) << 32) |
                                    (unsigned long long)(unsigned)~gj;
            float rs = rsum[r];
#pragma unroll
            for (int off = 8; off >= 1; off >>= 1) {
                rs += __shfl_xor_sync(0xFFFFFFFFu, rs, off);
                unsigned long long o = __shfl_xor_sync(0xFFFFFFFFu, rp, off);
                if (o > rp) rp = o;
            }
            if (tx == 0) {
                atomicAdd(&g_rowsum[ibase + i0 + r], rs);
                atomicMax(&g_rowmaxp[ibase + i0 + r], rp);
            }
        }
        // col reduce across ty via smem
        if (ty == 0) {
#pragma unroll
            for (int c = 0; c < 8; ++c) {
                unsigned km = ckmin[c];
                unsigned gi = (unsigned)(ibase + i0 + (int)(km & 7u));
                scsum[j0 + c] = csum[c];
                scmax[j0 + c] = (((unsigned long long)(~(km & 0xFFFFFFF8u))) << 32) |
                                (unsigned long long)(unsigned)~gi;
            }
        }
        __syncthreads();
        if (ty != 0) {
#pragma unroll
            for (int c = 0; c < 8; ++c) {
                unsigned km = ckmin[c];
                unsigned gi = (unsigned)(ibase + i0 + (int)(km & 7u));
                atomicAdd(&scsum[j0 + c], csum[c]);
                atomicMax(&scmax[j0 + c],
                          (((unsigned long long)(~(km & 0xFFFFFFF8u))) << 32) |
                          (unsigned long long)(unsigned)~gi);
            }
        }
        __syncthreads();
        if (ty == 0) {
#pragma unroll
            for (int c = 0; c < 8; ++c) {
                atomicAdd(&g_colsum[jbase + j0 + c], scsum[j0 + c]);
                atomicMax(&g_colmaxp[jbase + j0 + c], scmax[j0 + c]);
            }
        }
    } else {
        // ================= H branch: fp16 3-term mma.sync =================
        uint32_t sbase = smem_u32(smem);
        const int w = tid >> 5;
        const int lane = tid & 31;
        float* s_sxq = (float*)(smem + H_SXQ);
        float* s_syq = (float*)(smem + H_SYQ);
        float* s_csum = (float*)(smem + H_CSUM);
        float* s_rsum = (float*)(smem + H_RSUM);
        unsigned long long* s_cmax = (unsigned long long*)(smem + H_CMAX);
        unsigned long long* s_rmax = (unsigned long long*)(smem + H_RMAX);

#pragma unroll
        for (int t4 = 0; t4 < 4; ++t4) {
            const uint4* src = (t4 == 0) ? g_xh : (t4 == 1) ? g_xl
                             : (t4 == 2) ? g_yh : g_yl;
            int rbase = (t4 < 2) ? ibase : jbase;
            char* dst = smem + t4 * 16384;
            for (int k = tid; k < 1024; k += 256) {
                int row = k >> 3;
                int c = k & 7;
                uint4 v = src[(size_t)(rbase + row) * 8 + c];
                uint32_t bo = (uint32_t)(row * 128 + c * 16);
                *(uint4*)(dst + (bo ^ ((bo >> 3) & 0x70))) = v;
            }
        }
        if (tid < 128) {
            s_sxq[tid] = g_xsq[ibase + tid];
            s_syq[tid] = g_ysq[jbase + tid];
            s_csum[tid] = 0.f; s_rsum[tid] = 0.f;
            s_cmax[tid] = 0ull; s_rmax[tid] = 0ull;
        }
        __syncthreads();

        const int mblk = (w & 3) * 32;
        const int nblk = (w >> 2) * 64;
        const int mi = lane >> 3;
        const int l7 = lane & 7;

        uint32_t a_pre[2], b_pre[4];
#pragma unroll
        for (int mt = 0; mt < 2; ++mt)
            a_pre[mt] = (uint32_t)((mblk + mt * 16 + (mi & 1) * 8 + l7) * 128 + (mi >> 1) * 16);
#pragma unroll
        for (int p4 = 0; p4 < 4; ++p4)
            b_pre[p4] = (uint32_t)((nblk + p4 * 16 + (mi >> 1) * 8 + l7) * 128 + (mi & 1) * 16);

        float acc[2][8][4];
#pragma unroll
        for (int mt = 0; mt < 2; ++mt)
#pragma unroll
            for (int nt = 0; nt < 8; ++nt)
#pragma unroll
                for (int k = 0; k < 4; ++k) acc[mt][nt][k] = 0.f;

#pragma unroll
        for (int s = 0; s < 4; ++s) {
            const uint32_t kb = (uint32_t)s * 32u;
            uint32_t A[2][2][4];
#pragma unroll
            for (int t2 = 0; t2 < 2; ++t2) {
                const uint32_t xb = sbase + (uint32_t)t2 * 16384u;
#pragma unroll
                for (int mt = 0; mt < 2; ++mt) {
                    uint32_t o = a_pre[mt] + kb; o ^= (o >> 3) & 0x70u;
                    ldsm4(A[t2][mt][0], A[t2][mt][1], A[t2][mt][2], A[t2][mt][3], xb + o);
                }
            }
            uint32_t B[8][2];
#pragma unroll
            for (int p4 = 0; p4 < 4; ++p4) {
                uint32_t o = b_pre[p4] + kb; o ^= (o >> 3) & 0x70u;
                ldsm4(B[2 * p4][0], B[2 * p4][1], B[2 * p4 + 1][0], B[2 * p4 + 1][1],
                      sbase + 32768u + o);
            }
#pragma unroll
            for (int nt = 0; nt < 8; ++nt)
#pragma unroll
                for (int mt = 0; mt < 2; ++mt)
                    mma_f16(acc[mt][nt][0], acc[mt][nt][1], acc[mt][nt][2], acc[mt][nt][3],
                            A[0][mt][0], A[0][mt][1], A[0][mt][2], A[0][mt][3],
                            B[nt][0], B[nt][1]);
#pragma unroll
            for (int nt = 0; nt < 8; ++nt)
#pragma unroll
                for (int mt = 0; mt < 2; ++mt)
                    mma_f16(acc[mt][nt][0], acc[mt][nt][1], acc[mt][nt][2], acc[mt][nt][3],
                            A[1][mt][0], A[1][mt][1], A[1][mt][2], A[1][mt][3],
                            B[nt][0], B[nt][1]);
#pragma unroll
            for (int p4 = 0; p4 < 4; ++p4) {
                uint32_t o = b_pre[p4] + kb; o ^= (o >> 3) & 0x70u;
                ldsm4(B[2 * p4][0], B[2 * p4][1], B[2 * p4 + 1][0], B[2 * p4 + 1][1],
                      sbase + 49152u + o);
            }
#pragma unroll
            for (int nt = 0; nt < 8; ++nt)
#pragma unroll
                for (int mt = 0; mt < 2; ++mt)
                    mma_f16(acc[mt][nt][0], acc[mt][nt][1], acc[mt][nt][2], acc[mt][nt][3],
                            A[0][mt][0], A[0][mt][1], A[0][mt][2], A[0][mt][3],
                            B[nt][0], B[nt][1]);
        }

        // -------- slim fused epilogue v2 --------
        const int q = lane & 3;
        const int lr = lane >> 2;
        float rsum[4] = {0.f, 0.f, 0.f, 0.f};
        unsigned rkmin[4] = {0xFFFFFFFFu, 0xFFFFFFFFu, 0xFFFFFFFFu, 0xFFFFFFFFu};
        float xs2v[4];
#pragma unroll
        for (int ridx = 0; ridx < 4; ++ridx)
            xs2v[ridx] = C_L2E2 * s_sxq[mblk + (ridx >> 1) * 16 + (ridx & 1) * 8 + lr];

#pragma unroll
        for (int nt = 0; nt < 8; ++nt) {
            const int cbase = nblk + nt * 8 + 2 * q;
            const float yq0s = C_L2E2 * s_syq[cbase];
            const float yq1s = C_L2E2 * s_syq[cbase + 1];
            float cs0 = 0.f, cs1 = 0.f;
            unsigned ck0 = 0xFFFFFFFFu, ck1 = 0xFFFFFFFFu;
#pragma unroll
            for (int mt = 0; mt < 2; ++mt) {
#pragma unroll
                for (int h = 0; h < 2; ++h) {
                    const int ridx = mt * 2 + h;
                    const float xs = xs2v[ridx];
#pragma unroll
                    for (int u = 0; u < 2; ++u) {
                        float a = acc[mt][nt][h * 2 + u];
                        float s2 = fmaf(C_M2L2E2, a, xs + (u ? yq1s : yq0s));
                        unsigned bb = __float_as_uint(s2);
                        rkmin[ridx] = min(rkmin[ridx],
                                          (bb & 0xFFFFFFF0u) | (unsigned)(nt * 2 + u));
                        unsigned kc = (bb & 0xFFFFFFFCu) | (unsigned)ridx;
                        float d2 = sqrta(s2);
                        float pp = ex2a(-d2);
                        rsum[ridx] += pp;
                        if (u) { cs1 += pp; ck1 = min(ck1, kc); }
                        else   { cs0 += pp; ck0 = min(ck0, kc); }
                    }
                }
            }
            unsigned ri0 = ck0 & 3u, ri1 = ck1 & 3u;
            unsigned gi0 = (unsigned)(ibase + mblk + (int)(ri0 >> 1) * 16 + (int)(ri0 & 1) * 8 + lr);
            unsigned gi1 = (unsigned)(ibase + mblk + (int)(ri1 >> 1) * 16 + (int)(ri1 & 1) * 8 + lr);
            unsigned long long cmax0 = (((unsigned long long)(~(ck0 & 0xFFFFFFFCu))) << 32) |
                                       (unsigned long long)(unsigned)~gi0;
            unsigned long long cmax1 = (((unsigned long long)(~(ck1 & 0xFFFFFFFCu))) << 32) |
                                       (unsigned long long)(unsigned)~gi1;
#pragma unroll
            for (int off = 4; off < 32; off <<= 1) {
                cs0 += __shfl_xor_sync(0xFFFFFFFFu, cs0, off);
                cs1 += __shfl_xor_sync(0xFFFFFFFFu, cs1, off);
                unsigned long long o0 = __shfl_xor_sync(0xFFFFFFFFu, cmax0, off);
                unsigned long long o1 = __shfl_xor_sync(0xFFFFFFFFu, cmax1, off);
                if (o0 > cmax0) cmax0 = o0;
                if (o1 > cmax1) cmax1 = o1;
            }
            if (lane < 4) {
                atomicAdd(&s_csum[cbase], cs0);
                atomicAdd(&s_csum[cbase + 1], cs1);
                atomicMax(&s_cmax[cbase], cmax0);
                atomicMax(&s_cmax[cbase + 1], cmax1);
            }
        }
#pragma unroll
        for (int ridx = 0; ridx < 4; ++ridx) {
            unsigned km = rkmin[ridx];
            unsigned ci = km & 15u;
            unsigned gj = (unsigned)(jbase + nblk + (int)(ci >> 1) * 8 + 2 * q + (int)(ci & 1));
            unsigned long long rp = (((unsigned long long)(~(km & 0xFFFFFFF0u))) << 32) |
                                    (unsigned long long)(unsigned)~gj;
            float rs = rsum[ridx];
#pragma unroll
            for (int off = 1; off < 4; off <<= 1) {
                rs += __shfl_xor_sync(0xFFFFFFFFu, rs, off);
                unsigned long long o = __shfl_xor_sync(0xFFFFFFFFu, rp, off);
                if (o > rp) rp = o;
            }
            if (q == 0) {
                int r = mblk + (ridx >> 1) * 16 + (ridx & 1) * 8 + lr;
                atomicAdd(&s_rsum[r], rs);
                atomicMax(&s_rmax[r], rp);
            }
        }
        __syncthreads();
        if (tid < 128) {
            atomicAdd(&g_colsum[jbase + tid], s_csum[tid]);
            atomicMax(&g_colmaxp[jbase + tid], s_cmax[tid]);
            atomicAdd(&g_rowsum[ibase + tid], s_rsum[tid]);
            atomicMax(&g_rowmaxp[ibase + tid], s_rmax[tid]);
        }
    }
}

// ---------------- finalize 1: per-row/col lse, choice, lp ----------------
// stored hi32 = ~bits(s2_min) (low idx bits forced); s2 = (log2e*dist)^2
// dmin = ln2 * sqrt(s2_min); lp = -dmin - log(sum exp(-dist))
__global__ void finalize1_kernel() {
    int t = blockIdx.x * blockDim.x + threadIdx.x;
    if (t >= NN) return;
    {
        unsigned long long p = g_rowmaxp[t];
        float s2min = __uint_as_float(~(unsigned)(p >> 32));
        float dmin = C_LN2 * sqrtf(s2min);
        g_choice_rows[t] = (int)(~(unsigned)(p & 0xFFFFFFFFull));
        g_lp_rows[t] = -dmin - logf(g_rowsum[t]);
    }
    {
        unsigned long long p = g_colmaxp[t];
        float s2min = __uint_as_float(~(unsigned)(p >> 32));
        float dmin = C_LN2 * sqrtf(s2min);
        g_choice_cols[t] = (int)(~(unsigned)(p & 0xFFFFFFFFull));
        g_lp_cols[t] = -dmin - logf(g_colsum[t]);
    }
}

// ---------------- finalize 2: mutual match + outputs ----------------
// out (float32): [0:M) log_probs, [M:3M) dmatches (cc, j), [3M:4M) mutual
__global__ void finalize2_kernel(float* __restrict__ out) {
    int j = blockIdx.x * blockDim.x + threadIdx.x;
    if (j >= MM) return;
    int cc = g_choice_cols[j];
    bool mut = (g_choice_rows[cc] == j);
    out[j] = mut ? (g_lp_rows[cc] + g_lp_cols[j]) : 0.f;
    out[MM + 2 * j]     = (float)cc;
    out[MM + 2 * j + 1] = (float)j;
    out[3 * MM + j] = mut ? 1.f : 0.f;
}

extern "C" void kernel_launch(void* const* d_in, const int* in_sizes, int n_in,
                              void* d_out, int out_size) {
    const float* x = (const float*)d_in[0];
    const float* y = (const float*)d_in[1];
    float* out = (float*)d_out;

    static int smem_set = 0;
    if (!smem_set) {
        cudaFuncSetAttribute(matcher_main_kernel,
                             cudaFuncAttributeMaxDynamicSharedMemorySize, SMEM_TOTAL);
        smem_set = 1;
    }

    prep_kernel<<<(2 * NN + 255) / 256, 256>>>(x, y);
    dim3 grid(NTILE, NTILE);
    matcher_main_kernel<<<grid, 256, SMEM_TOTAL>>>(x, y);
    finalize1_kernel<<<(NN + 255) / 256, 256>>>();
    finalize2_kernel<<<(MM + 255) / 256, 256>>>(out);
}